// round 1
// baseline (speedup 1.0000x reference)
#include <cuda_runtime.h>
#include <math.h>

#define BATCH   2
#define SEQLEN  2048
#define DMODEL  1024
#define DINNER  2048
#define NHEADS  32
#define HEADDIM 64
#define DSTATE  128
#define CHUNK   256
#define NCHUNK  (SEQLEN / CHUNK)       // 8
#define DPROJ   4384                   // 2*DINNER + 2*DSTATE + NHEADS
#define CONVDIM 2304                   // DINNER + 2*DSTATE
#define DCONV   4
#define ROWS    (BATCH * SEQLEN)       // 4096
#define BHC     (BATCH * NHEADS * NCHUNK)   // 512
#define LN_EPS  1e-5f

// ---------------- scratch (static device globals; no allocations) ----------------
__device__ float g_zxbcdt[(size_t)ROWS * DPROJ];                       // 71.8 MB
__device__ float g_xbc[(size_t)ROWS * CONVDIM];                        // 37.7 MB
__device__ float g_dt[(size_t)ROWS * NHEADS];
__device__ float g_dA[(size_t)ROWS * NHEADS];
__device__ float g_Acs[(size_t)BHC * CHUNK];
__device__ float g_scores[(size_t)BHC * CHUNK * CHUNK];                // 134 MB
__device__ float g_cst[(size_t)BHC * HEADDIM * DSTATE];                // 16.8 MB
__device__ float g_pst[(size_t)BHC * HEADDIM * DSTATE];                // 16.8 MB
__device__ float g_Y[(size_t)ROWS * DINNER];                           // 33.5 MB
__device__ float g_Yn[(size_t)ROWS * DINNER];                          // 33.5 MB

// ---------------- generic fp32 GEMM: C[m,n] = sum_k A[m,k] * W[n,k] ----------------
// A: [M,K] row-major, W: [N,K] row-major. 64x64 block tile, BK=16, 4x4 micro.
__global__ void gemm_tn_kernel(const float* __restrict__ A,
                               const float* __restrict__ W,
                               float* __restrict__ C,
                               int M, int N, int K)
{
    __shared__ float sA[16][64];
    __shared__ float sW[16][64];
    int tid = threadIdx.x;
    int tx = tid & 15, ty = tid >> 4;
    int m0 = blockIdx.y * 64, n0 = blockIdx.x * 64;
    float acc[4][4] = {};
    int lr = tid >> 2;            // 0..63
    int lk = (tid & 3) * 4;       // 0,4,8,12
    for (int k0 = 0; k0 < K; k0 += 16) {
        int am = m0 + lr;
        int wn = n0 + lr;
        #pragma unroll
        for (int j = 0; j < 4; j++) {
            sA[lk + j][lr] = (am < M) ? A[(size_t)am * K + k0 + lk + j] : 0.f;
            sW[lk + j][lr] = (wn < N) ? W[(size_t)wn * K + k0 + lk + j] : 0.f;
        }
        __syncthreads();
        #pragma unroll
        for (int k = 0; k < 16; k++) {
            float a[4], b[4];
            #pragma unroll
            for (int i = 0; i < 4; i++) a[i] = sA[k][ty * 4 + i];
            #pragma unroll
            for (int i = 0; i < 4; i++) b[i] = sW[k][tx * 4 + i];
            #pragma unroll
            for (int i = 0; i < 4; i++)
                #pragma unroll
                for (int j = 0; j < 4; j++)
                    acc[i][j] = fmaf(a[i], b[j], acc[i][j]);
        }
        __syncthreads();
    }
    #pragma unroll
    for (int i = 0; i < 4; i++) {
        int m = m0 + ty * 4 + i;
        if (m >= M) continue;
        #pragma unroll
        for (int j = 0; j < 4; j++) {
            int n = n0 + tx * 4 + j;
            if (n < N) C[(size_t)m * N + n] = acc[i][j];
        }
    }
}

// ---------------- conv1d (causal, width 4) + SiLU ----------------
__global__ void conv_silu_kernel(const float* __restrict__ conv_w,
                                 const float* __restrict__ conv_b)
{
    int idx = blockIdx.x * blockDim.x + threadIdx.x;
    if (idx >= ROWS * CONVDIM) return;
    int c = idx % CONVDIM;
    int row = idx / CONVDIM;         // b*L + l
    int l = row % SEQLEN;
    float acc = conv_b[c];
    #pragma unroll
    for (int k = 0; k < DCONV; k++) {
        int lp = l - (DCONV - 1) + k;
        if (lp >= 0)
            acc = fmaf(g_zxbcdt[(size_t)(row - (l - lp)) * DPROJ + DINNER + c],
                       conv_w[c * DCONV + k], acc);
    }
    g_xbc[idx] = acc / (1.f + expf(-acc));
}

// ---------------- dt = softplus(raw + bias); dA = -exp(A_log)*dt ----------------
__global__ void dt_kernel(const float* __restrict__ dt_bias,
                          const float* __restrict__ A_log)
{
    int idx = blockIdx.x * blockDim.x + threadIdx.x;
    if (idx >= ROWS * NHEADS) return;
    int h = idx % NHEADS;
    int row = idx / NHEADS;
    float x = g_zxbcdt[(size_t)row * DPROJ + (DPROJ - NHEADS) + h] + dt_bias[h];
    float dtv = (x > 20.f) ? x : log1pf(expf(x));
    g_dt[idx] = dtv;
    g_dA[idx] = -expf(A_log[h]) * dtv;
}

// ---------------- per-chunk inclusive cumsum of dA (Hillis-Steele) ----------------
__global__ void cumsum_kernel()
{
    int bid = blockIdx.x;            // (b*H + h)*NC + c
    int c = bid % NCHUNK;
    int bh = bid / NCHUNK;
    int h = bh % NHEADS;
    int b = bh / NHEADS;
    int t = threadIdx.x;
    __shared__ float s[CHUNK];
    int l = c * CHUNK + t;
    s[t] = g_dA[(size_t)(b * SEQLEN + l) * NHEADS + h];
    __syncthreads();
    for (int off = 1; off < CHUNK; off <<= 1) {
        float v = (t >= off) ? s[t - off] : 0.f;
        __syncthreads();
        s[t] += v;
        __syncthreads();
    }
    g_Acs[(size_t)bid * CHUNK + t] = s[t];
}

// ---------------- scores S[l,s] = (C[l]·B[s]) * exp(Acs[l]-Acs[s]), s<=l ----------------
// grid: (stile 4, ltile 4, bhc 512). Upper tiles (stile>ltile) skipped entirely
// (never written, never read by y_kernel).
__global__ void scores_kernel()
{
    int stile = blockIdx.x, ltile = blockIdx.y;
    if (stile > ltile) return;
    int bhc = blockIdx.z;
    int c = bhc % NCHUNK;
    int bh = bhc / NCHUNK;
    int b = bh / NHEADS;
    int tid = threadIdx.x;
    int tx = tid & 15, ty = tid >> 4;
    int l0 = ltile * 64, s0 = stile * 64;
    __shared__ float sC[16][64];
    __shared__ float sB[16][64];
    float acc[4][4] = {};
    int lr = tid >> 2, lk = (tid & 3) * 4;
    size_t rowbase = (size_t)(b * SEQLEN + c * CHUNK);
    for (int k0 = 0; k0 < DSTATE; k0 += 16) {
        #pragma unroll
        for (int j = 0; j < 4; j++) {
            sC[lk + j][lr] = g_xbc[(rowbase + l0 + lr) * CONVDIM + DINNER + DSTATE + k0 + lk + j];
            sB[lk + j][lr] = g_xbc[(rowbase + s0 + lr) * CONVDIM + DINNER + k0 + lk + j];
        }
        __syncthreads();
        #pragma unroll
        for (int k = 0; k < 16; k++) {
            float a[4], bb[4];
            #pragma unroll
            for (int i = 0; i < 4; i++) a[i] = sC[k][ty * 4 + i];
            #pragma unroll
            for (int i = 0; i < 4; i++) bb[i] = sB[k][tx * 4 + i];
            #pragma unroll
            for (int i = 0; i < 4; i++)
                #pragma unroll
                for (int j = 0; j < 4; j++)
                    acc[i][j] = fmaf(a[i], bb[j], acc[i][j]);
        }
        __syncthreads();
    }
    size_t abase = (size_t)bhc * CHUNK;
    float Al[4], As[4];
    #pragma unroll
    for (int i = 0; i < 4; i++) Al[i] = g_Acs[abase + l0 + ty * 4 + i];
    #pragma unroll
    for (int j = 0; j < 4; j++) As[j] = g_Acs[abase + s0 + tx * 4 + j];
    size_t obase = (size_t)bhc * CHUNK * CHUNK;
    #pragma unroll
    for (int i = 0; i < 4; i++) {
        int l = l0 + ty * 4 + i;
        #pragma unroll
        for (int j = 0; j < 4; j++) {
            int s = s0 + tx * 4 + j;
            float v = (s <= l) ? acc[i][j] * expf(Al[i] - As[j]) : 0.f;
            g_scores[obase + (size_t)l * CHUNK + s] = v;
        }
    }
}

// ---------------- chunk states: st[p,n] = sum_s B[s,n]*exp(Alast-Acs[s])*X[s,p]*dt[s] ----------------
__global__ void cstate_kernel()
{
    int bhc = blockIdx.x;
    int c = bhc % NCHUNK;
    int bh = bhc / NCHUNK;
    int h = bh % NHEADS;
    int b = bh / NHEADS;
    int tid = threadIdx.x;
    int tx = tid & 15, ty = tid >> 4;
    __shared__ float sX[16][64];    // [s][p], prescaled
    __shared__ float sB[16][128];   // [s][n]
    float acc[4][8] = {};
    size_t rowbase = (size_t)(b * SEQLEN + c * CHUNK);
    size_t abase = (size_t)bhc * CHUNK;
    float Alast = g_Acs[abase + CHUNK - 1];
    int ls = tid >> 4;              // 0..15
    int lp4 = (tid & 15) * 4;
    int ln8 = (tid & 15) * 8;
    for (int s0 = 0; s0 < CHUNK; s0 += 16) {
        int srow = s0 + ls;
        float w = g_dt[(rowbase + srow) * NHEADS + h] * expf(Alast - g_Acs[abase + srow]);
        #pragma unroll
        for (int j = 0; j < 4; j++)
            sX[ls][lp4 + j] = g_xbc[(rowbase + srow) * CONVDIM + h * HEADDIM + lp4 + j] * w;
        #pragma unroll
        for (int j = 0; j < 8; j++)
            sB[ls][ln8 + j] = g_xbc[(rowbase + srow) * CONVDIM + DINNER + ln8 + j];
        __syncthreads();
        #pragma unroll
        for (int k = 0; k < 16; k++) {
            float a[4], bb[8];
            #pragma unroll
            for (int i = 0; i < 4; i++) a[i] = sX[k][ty * 4 + i];
            #pragma unroll
            for (int j = 0; j < 8; j++) bb[j] = sB[k][tx * 8 + j];
            #pragma unroll
            for (int i = 0; i < 4; i++)
                #pragma unroll
                for (int j = 0; j < 8; j++)
                    acc[i][j] = fmaf(a[i], bb[j], acc[i][j]);
        }
        __syncthreads();
    }
    size_t obase = (size_t)bhc * HEADDIM * DSTATE;
    #pragma unroll
    for (int i = 0; i < 4; i++)
        #pragma unroll
        for (int j = 0; j < 8; j++)
            g_cst[obase + (size_t)(ty * 4 + i) * DSTATE + tx * 8 + j] = acc[i][j];
}

// ---------------- inter-chunk scan over 8 chunks ----------------
__global__ void scan_kernel()
{
    int bh = blockIdx.x;             // 0..63
    int t = threadIdx.x;
    float R[32];
    #pragma unroll
    for (int e = 0; e < 32; e++) R[e] = 0.f;
    for (int c = 0; c < NCHUNK; c++) {
        size_t bhc = (size_t)bh * NCHUNK + c;
        float decay = expf(g_Acs[bhc * CHUNK + CHUNK - 1]);
        size_t base = bhc * HEADDIM * DSTATE;
        #pragma unroll
        for (int e = 0; e < 32; e++) {
            size_t idx = base + t + (size_t)e * 256;
            g_pst[idx] = R[e];
            R[e] = fmaf(R[e], decay, g_cst[idx]);
        }
    }
}

// ---------------- Y = S@X + exp(Acs[l]) * C @ prev_state^T ----------------
// grid: (ltile 4, bhc 512). block computes [64 l][64 p].
__global__ void y_kernel()
{
    int ltile = blockIdx.x;
    int bhc = blockIdx.y;
    int c = bhc % NCHUNK;
    int bh = bhc / NCHUNK;
    int h = bh % NHEADS;
    int b = bh / NHEADS;
    int tid = threadIdx.x;
    int tx = tid & 15, ty = tid >> 4;
    int l0 = ltile * 64;
    __shared__ float s0a[16][64];    // sS: [s][l]   / sC: [n][l]
    __shared__ float s0b[16][64];    // sX: [s][p]   / sP: [n][p]
    float acc[4][4] = {};
    size_t rowbase = (size_t)(b * SEQLEN + c * CHUNK);
    size_t sc_base = (size_t)bhc * CHUNK * CHUNK;
    size_t abase = (size_t)bhc * CHUNK;
    size_t pbase = (size_t)bhc * HEADDIM * DSTATE;
    int ld_l = tid >> 2, ld_k4 = (tid & 3) * 4;
    int sx_s = tid >> 4, sx_p = (tid & 15) * 4;

    // part 1: diag = S @ X  (only causal tiles: s0 <= l0+63)
    for (int s0 = 0; s0 < l0 + 64; s0 += 16) {
        #pragma unroll
        for (int j = 0; j < 4; j++)
            s0a[ld_k4 + j][ld_l] = g_scores[sc_base + (size_t)(l0 + ld_l) * CHUNK + s0 + ld_k4 + j];
        int srow = s0 + sx_s;
        float dtv = g_dt[(rowbase + srow) * NHEADS + h];
        #pragma unroll
        for (int j = 0; j < 4; j++)
            s0b[sx_s][sx_p + j] = g_xbc[(rowbase + srow) * CONVDIM + h * HEADDIM + sx_p + j] * dtv;
        __syncthreads();
        #pragma unroll
        for (int k = 0; k < 16; k++) {
            float a[4], bb[4];
            #pragma unroll
            for (int i = 0; i < 4; i++) a[i] = s0a[k][ty * 4 + i];
            #pragma unroll
            for (int i = 0; i < 4; i++) bb[i] = s0b[k][tx * 4 + i];
            #pragma unroll
            for (int i = 0; i < 4; i++)
                #pragma unroll
                for (int j = 0; j < 4; j++)
                    acc[i][j] = fmaf(a[i], bb[j], acc[i][j]);
        }
        __syncthreads();
    }

    // part 2: off = (C*exp(Acs)) @ prev_state^T
    float eA = expf(g_Acs[abase + l0 + ld_l]);
    for (int n0 = 0; n0 < DSTATE; n0 += 16) {
        #pragma unroll
        for (int j = 0; j < 4; j++)
            s0a[ld_k4 + j][ld_l] =
                g_xbc[(rowbase + l0 + ld_l) * CONVDIM + DINNER + DSTATE + n0 + ld_k4 + j] * eA;
        #pragma unroll
        for (int j = 0; j < 4; j++)
            s0b[ld_k4 + j][ld_l] = g_pst[pbase + (size_t)ld_l * DSTATE + n0 + ld_k4 + j];
        __syncthreads();
        #pragma unroll
        for (int k = 0; k < 16; k++) {
            float a[4], bb[4];
            #pragma unroll
            for (int i = 0; i < 4; i++) a[i] = s0a[k][ty * 4 + i];
            #pragma unroll
            for (int i = 0; i < 4; i++) bb[i] = s0b[k][tx * 4 + i];
            #pragma unroll
            for (int i = 0; i < 4; i++)
                #pragma unroll
                for (int j = 0; j < 4; j++)
                    acc[i][j] = fmaf(a[i], bb[j], acc[i][j]);
        }
        __syncthreads();
    }

    #pragma unroll
    for (int i = 0; i < 4; i++)
        #pragma unroll
        for (int j = 0; j < 4; j++)
            g_Y[(rowbase + l0 + ty * 4 + i) * DINNER + h * HEADDIM + tx * 4 + j] = acc[i][j];
}

// ---------------- layernorm (population var) * ln_w * silu(z) ----------------
__global__ void ln_gate_kernel(const float* __restrict__ ln_w)
{
    int row = blockIdx.x;
    int t = threadIdx.x;
    __shared__ float red[256];
    float vals[8];
    float sum = 0.f, sq = 0.f;
    #pragma unroll
    for (int i = 0; i < 8; i++) {
        float v = g_Y[(size_t)row * DINNER + t + i * 256];
        vals[i] = v;
        sum += v;
        sq = fmaf(v, v, sq);
    }
    red[t] = sum;
    __syncthreads();
    for (int off = 128; off; off >>= 1) {
        if (t < off) red[t] += red[t + off];
        __syncthreads();
    }
    float mean = red[0] / DINNER;
    __syncthreads();
    red[t] = sq;
    __syncthreads();
    for (int off = 128; off; off >>= 1) {
        if (t < off) red[t] += red[t + off];
        __syncthreads();
    }
    float var = red[0] / DINNER - mean * mean;
    float rstd = rsqrtf(var + LN_EPS);
    #pragma unroll
    for (int i = 0; i < 8; i++) {
        int j = t + i * 256;
        float z = g_zxbcdt[(size_t)row * DPROJ + j];
        float gate = z / (1.f + expf(-z));
        g_Yn[(size_t)row * DINNER + j] = (vals[i] - mean) * rstd * ln_w[j] * gate;
    }
}

// ---------------- launch ----------------
extern "C" void kernel_launch(void* const* d_in, const int* in_sizes, int n_in,
                              void* d_out, int out_size)
{
    const float* u          = (const float*)d_in[0];
    const float* in_proj_w  = (const float*)d_in[1];
    const float* conv_w     = (const float*)d_in[2];
    const float* conv_b     = (const float*)d_in[3];
    const float* dt_bias    = (const float*)d_in[4];
    const float* A_log      = (const float*)d_in[5];
    const float* ln_w       = (const float*)d_in[6];
    const float* out_proj_w = (const float*)d_in[7];
    float* out = (float*)d_out;

    float *zx_ptr, *yn_ptr;
    cudaGetSymbolAddress((void**)&zx_ptr, g_zxbcdt);
    cudaGetSymbolAddress((void**)&yn_ptr, g_Yn);

    // 1. in_proj: [4096,4384] = u[4096,1024] @ W^T
    gemm_tn_kernel<<<dim3((DPROJ + 63) / 64, ROWS / 64), 256>>>(
        u, in_proj_w, zx_ptr, ROWS, DPROJ, DMODEL);
    // 2. conv + silu
    conv_silu_kernel<<<(ROWS * CONVDIM + 255) / 256, 256>>>(conv_w, conv_b);
    // 3. dt / dA
    dt_kernel<<<(ROWS * NHEADS + 255) / 256, 256>>>(dt_bias, A_log);
    // 4. per-chunk cumsum
    cumsum_kernel<<<BHC, CHUNK>>>();
    // 5. scores
    scores_kernel<<<dim3(4, 4, BHC), 256>>>();
    // 6. chunk states
    cstate_kernel<<<BHC, 256>>>();
    // 7. inter-chunk scan
    scan_kernel<<<BATCH * NHEADS, 256>>>();
    // 8. Y = diag + off
    y_kernel<<<dim3(4, BHC), 256>>>();
    // 9. LN + gate
    ln_gate_kernel<<<ROWS, 256>>>(ln_w);
    // 10. out_proj: [4096,1024] = Yn[4096,2048] @ W^T
    gemm_tn_kernel<<<dim3(DMODEL / 64, ROWS / 64), 256>>>(
        yn_ptr, out_proj_w, out, ROWS, DMODEL, DINNER);
}

// round 2
// speedup vs baseline: 1.7337x; 1.7337x over previous
#include <cuda_runtime.h>
#include <math.h>
#include <mma.h>

using namespace nvcuda;

#define BATCH   2
#define SEQLEN  2048
#define DMODEL  1024
#define DINNER  2048
#define NHEADS  32
#define HEADDIM 64
#define DSTATE  128
#define CHUNK   256
#define NCHUNK  (SEQLEN / CHUNK)       // 8
#define DPROJ   4384                   // 2*DINNER + 2*DSTATE + NHEADS
#define CONVDIM 2304                   // DINNER + 2*DSTATE
#define DCONV   4
#define ROWS    (BATCH * SEQLEN)       // 4096
#define BHC     (BATCH * NHEADS * NCHUNK)   // 512
#define LN_EPS  1e-5f

// ---------------- scratch (static device globals; no allocations) ----------------
__device__ float g_zxbcdt[(size_t)ROWS * DPROJ];                       // 71.8 MB
__device__ float g_xbc[(size_t)ROWS * CONVDIM];                        // 37.7 MB
__device__ float g_dt[(size_t)ROWS * NHEADS];
__device__ float g_dA[(size_t)ROWS * NHEADS];
__device__ float g_Acs[(size_t)BHC * CHUNK];
__device__ float g_scores[(size_t)BHC * CHUNK * CHUNK];                // 134 MB
__device__ float g_cst[(size_t)BHC * HEADDIM * DSTATE];                // 16.8 MB
__device__ float g_pst[(size_t)BHC * HEADDIM * DSTATE];                // 16.8 MB
__device__ float g_Y[(size_t)ROWS * DINNER];                           // 33.5 MB
__device__ float g_Yn[(size_t)ROWS * DINNER];                          // 33.5 MB

// =============== tf32 tensor-core GEMM: C[m,n] = sum_k A[m,k] * W[n,k] ===============
// A: [M,K] row-major, W: [N,K] row-major (i.e. col-major [K,N]).
// Block tile 128x64, BK=16, 8 warps as 4(M) x 2(N), each warp 32x32 via 2x2 wmma frags.
// Requirements: M % 128 == 0, K % 16 == 0. N tail handled by guarded epilogue.
#define TM 128
#define TN 64
#define TK 16
#define SLD (TK + 4)   // shared leading dim (20, multiple of 4, keeps float4 alignment)

__global__ __launch_bounds__(256) void gemm_tf32_kernel(
    const float* __restrict__ A,
    const float* __restrict__ W,
    float* __restrict__ C,
    int M, int N, int K)
{
    __shared__ float sA[TM][SLD];
    __shared__ float sW[TN][SLD];
    __shared__ float sOut[8][16][SLD];   // epilogue staging for boundary tiles

    int tid  = threadIdx.x;
    int warp = tid >> 5;
    int wm   = (warp >> 1) * 32;
    int wn   = (warp & 1) * 32;
    int m0   = blockIdx.y * TM;
    int n0   = blockIdx.x * TN;

    wmma::fragment<wmma::accumulator, 16, 16, 8, float> acc[2][2];
    #pragma unroll
    for (int i = 0; i < 2; i++)
        #pragma unroll
        for (int j = 0; j < 2; j++)
            wmma::fill_fragment(acc[i][j], 0.0f);

    // loader mapping
    int fa0 = tid * 2;                // A: 512 float4 total, 2 per thread
    int ar0 = fa0 >> 2,      ak0 = (fa0 & 3) * 4;
    int ar1 = (fa0 + 1) >> 2, ak1 = ((fa0 + 1) & 3) * 4;
    int wr  = tid >> 2,      wk  = (tid & 3) * 4;   // W: 256 float4, 1 per thread

    const float4 z4 = make_float4(0.f, 0.f, 0.f, 0.f);

    // prefetch k0 = 0
    float4 pa0 = *(const float4*)&A[(size_t)(m0 + ar0) * K + ak0];
    float4 pa1 = *(const float4*)&A[(size_t)(m0 + ar1) * K + ak1];
    float4 pw  = (n0 + wr < N) ? *(const float4*)&W[(size_t)(n0 + wr) * K + wk] : z4;

    int ktiles = K / TK;
    for (int kt = 0; kt < ktiles; kt++) {
        *(float4*)&sA[ar0][ak0] = pa0;
        *(float4*)&sA[ar1][ak1] = pa1;
        *(float4*)&sW[wr][wk]   = pw;
        __syncthreads();

        if (kt + 1 < ktiles) {
            int k0 = (kt + 1) * TK;
            pa0 = *(const float4*)&A[(size_t)(m0 + ar0) * K + k0 + ak0];
            pa1 = *(const float4*)&A[(size_t)(m0 + ar1) * K + k0 + ak1];
            pw  = (n0 + wr < N) ? *(const float4*)&W[(size_t)(n0 + wr) * K + k0 + wk] : z4;
        }

        #pragma unroll
        for (int kk = 0; kk < TK; kk += 8) {
            wmma::fragment<wmma::matrix_a, 16, 16, 8, wmma::precision::tf32, wmma::row_major> af[2];
            wmma::fragment<wmma::matrix_b, 16, 16, 8, wmma::precision::tf32, wmma::col_major> bf[2];
            #pragma unroll
            for (int i = 0; i < 2; i++) {
                wmma::load_matrix_sync(af[i], &sA[wm + 16 * i][kk], SLD);
                #pragma unroll
                for (int t = 0; t < af[i].num_elements; t++)
                    af[i].x[t] = wmma::__float_to_tf32(af[i].x[t]);
            }
            #pragma unroll
            for (int j = 0; j < 2; j++) {
                wmma::load_matrix_sync(bf[j], &sW[wn + 16 * j][kk], SLD);
                #pragma unroll
                for (int t = 0; t < bf[j].num_elements; t++)
                    bf[j].x[t] = wmma::__float_to_tf32(bf[j].x[t]);
            }
            #pragma unroll
            for (int i = 0; i < 2; i++)
                #pragma unroll
                for (int j = 0; j < 2; j++)
                    wmma::mma_sync(acc[i][j], af[i], bf[j], acc[i][j]);
        }
        __syncthreads();
    }

    if (n0 + TN <= N) {
        // interior tile: direct wmma store to global
        #pragma unroll
        for (int i = 0; i < 2; i++)
            #pragma unroll
            for (int j = 0; j < 2; j++)
                wmma::store_matrix_sync(
                    &C[(size_t)(m0 + wm + 16 * i) * N + n0 + wn + 16 * j],
                    acc[i][j], N, wmma::mem_row_major);
    } else {
        // boundary tile (N tail): stage through shared, guarded scalar writes
        int lane = tid & 31;
        #pragma unroll
        for (int i = 0; i < 2; i++)
            #pragma unroll
            for (int j = 0; j < 2; j++) {
                wmma::store_matrix_sync(&sOut[warp][0][0], acc[i][j], SLD, wmma::mem_row_major);
                __syncwarp();
                #pragma unroll
                for (int e = 0; e < 8; e++) {
                    int idx = lane + e * 32;           // 0..255
                    int r = idx >> 4, cl = idx & 15;
                    int gn = n0 + wn + 16 * j + cl;
                    if (gn < N)
                        C[(size_t)(m0 + wm + 16 * i + r) * N + gn] = sOut[warp][r][cl];
                }
                __syncwarp();
            }
    }
}

// ---------------- conv1d (causal, width 4) + SiLU ----------------
__global__ void conv_silu_kernel(const float* __restrict__ conv_w,
                                 const float* __restrict__ conv_b)
{
    int idx = blockIdx.x * blockDim.x + threadIdx.x;
    if (idx >= ROWS * CONVDIM) return;
    int c = idx % CONVDIM;
    int row = idx / CONVDIM;         // b*L + l
    int l = row % SEQLEN;
    float acc = conv_b[c];
    #pragma unroll
    for (int k = 0; k < DCONV; k++) {
        int lp = l - (DCONV - 1) + k;
        if (lp >= 0)
            acc = fmaf(g_zxbcdt[(size_t)(row - (l - lp)) * DPROJ + DINNER + c],
                       conv_w[c * DCONV + k], acc);
    }
    g_xbc[idx] = acc / (1.f + expf(-acc));
}

// ---------------- dt = softplus(raw + bias); dA = -exp(A_log)*dt ----------------
__global__ void dt_kernel(const float* __restrict__ dt_bias,
                          const float* __restrict__ A_log)
{
    int idx = blockIdx.x * blockDim.x + threadIdx.x;
    if (idx >= ROWS * NHEADS) return;
    int h = idx % NHEADS;
    int row = idx / NHEADS;
    float x = g_zxbcdt[(size_t)row * DPROJ + (DPROJ - NHEADS) + h] + dt_bias[h];
    float dtv = (x > 20.f) ? x : log1pf(expf(x));
    g_dt[idx] = dtv;
    g_dA[idx] = -expf(A_log[h]) * dtv;
}

// ---------------- per-chunk inclusive cumsum of dA (Hillis-Steele) ----------------
__global__ void cumsum_kernel()
{
    int bid = blockIdx.x;            // (b*H + h)*NC + c
    int c = bid % NCHUNK;
    int bh = bid / NCHUNK;
    int h = bh % NHEADS;
    int b = bh / NHEADS;
    int t = threadIdx.x;
    __shared__ float s[CHUNK];
    int l = c * CHUNK + t;
    s[t] = g_dA[(size_t)(b * SEQLEN + l) * NHEADS + h];
    __syncthreads();
    for (int off = 1; off < CHUNK; off <<= 1) {
        float v = (t >= off) ? s[t - off] : 0.f;
        __syncthreads();
        s[t] += v;
        __syncthreads();
    }
    g_Acs[(size_t)bid * CHUNK + t] = s[t];
}

// ---------------- scores S[l,s] = (C[l]·B[s]) * exp(Acs[l]-Acs[s]), s<=l ----------------
__global__ void scores_kernel()
{
    int stile = blockIdx.x, ltile = blockIdx.y;
    if (stile > ltile) return;
    int bhc = blockIdx.z;
    int c = bhc % NCHUNK;
    int bh = bhc / NCHUNK;
    int b = bh / NHEADS;
    int tid = threadIdx.x;
    int tx = tid & 15, ty = tid >> 4;
    int l0 = ltile * 64, s0 = stile * 64;
    __shared__ float sC[16][64];
    __shared__ float sB[16][64];
    float acc[4][4] = {};
    int lr = tid >> 2, lk = (tid & 3) * 4;
    size_t rowbase = (size_t)(b * SEQLEN + c * CHUNK);
    for (int k0 = 0; k0 < DSTATE; k0 += 16) {
        #pragma unroll
        for (int j = 0; j < 4; j++) {
            sC[lk + j][lr] = g_xbc[(rowbase + l0 + lr) * CONVDIM + DINNER + DSTATE + k0 + lk + j];
            sB[lk + j][lr] = g_xbc[(rowbase + s0 + lr) * CONVDIM + DINNER + k0 + lk + j];
        }
        __syncthreads();
        #pragma unroll
        for (int k = 0; k < 16; k++) {
            float a[4], bb[4];
            #pragma unroll
            for (int i = 0; i < 4; i++) a[i] = sC[k][ty * 4 + i];
            #pragma unroll
            for (int i = 0; i < 4; i++) bb[i] = sB[k][tx * 4 + i];
            #pragma unroll
            for (int i = 0; i < 4; i++)
                #pragma unroll
                for (int j = 0; j < 4; j++)
                    acc[i][j] = fmaf(a[i], bb[j], acc[i][j]);
        }
        __syncthreads();
    }
    size_t abase = (size_t)bhc * CHUNK;
    float Al[4], As[4];
    #pragma unroll
    for (int i = 0; i < 4; i++) Al[i] = g_Acs[abase + l0 + ty * 4 + i];
    #pragma unroll
    for (int j = 0; j < 4; j++) As[j] = g_Acs[abase + s0 + tx * 4 + j];
    size_t obase = (size_t)bhc * CHUNK * CHUNK;
    #pragma unroll
    for (int i = 0; i < 4; i++) {
        int l = l0 + ty * 4 + i;
        #pragma unroll
        for (int j = 0; j < 4; j++) {
            int s = s0 + tx * 4 + j;
            float v = (s <= l) ? acc[i][j] * expf(Al[i] - As[j]) : 0.f;
            g_scores[obase + (size_t)l * CHUNK + s] = v;
        }
    }
}

// ---------------- chunk states ----------------
__global__ void cstate_kernel()
{
    int bhc = blockIdx.x;
    int c = bhc % NCHUNK;
    int bh = bhc / NCHUNK;
    int h = bh % NHEADS;
    int b = bh / NHEADS;
    int tid = threadIdx.x;
    int tx = tid & 15, ty = tid >> 4;
    __shared__ float sX[16][64];    // [s][p], prescaled
    __shared__ float sB[16][128];   // [s][n]
    float acc[4][8] = {};
    size_t rowbase = (size_t)(b * SEQLEN + c * CHUNK);
    size_t abase = (size_t)bhc * CHUNK;
    float Alast = g_Acs[abase + CHUNK - 1];
    int ls = tid >> 4;              // 0..15
    int lp4 = (tid & 15) * 4;
    int ln8 = (tid & 15) * 8;
    for (int s0 = 0; s0 < CHUNK; s0 += 16) {
        int srow = s0 + ls;
        float w = g_dt[(rowbase + srow) * NHEADS + h] * expf(Alast - g_Acs[abase + srow]);
        #pragma unroll
        for (int j = 0; j < 4; j++)
            sX[ls][lp4 + j] = g_xbc[(rowbase + srow) * CONVDIM + h * HEADDIM + lp4 + j] * w;
        #pragma unroll
        for (int j = 0; j < 8; j++)
            sB[ls][ln8 + j] = g_xbc[(rowbase + srow) * CONVDIM + DINNER + ln8 + j];
        __syncthreads();
        #pragma unroll
        for (int k = 0; k < 16; k++) {
            float a[4], bb[8];
            #pragma unroll
            for (int i = 0; i < 4; i++) a[i] = sX[k][ty * 4 + i];
            #pragma unroll
            for (int j = 0; j < 8; j++) bb[j] = sB[k][tx * 8 + j];
            #pragma unroll
            for (int i = 0; i < 4; i++)
                #pragma unroll
                for (int j = 0; j < 8; j++)
                    acc[i][j] = fmaf(a[i], bb[j], acc[i][j]);
        }
        __syncthreads();
    }
    size_t obase = (size_t)bhc * HEADDIM * DSTATE;
    #pragma unroll
    for (int i = 0; i < 4; i++)
        #pragma unroll
        for (int j = 0; j < 8; j++)
            g_cst[obase + (size_t)(ty * 4 + i) * DSTATE + tx * 8 + j] = acc[i][j];
}

// ---------------- inter-chunk scan over 8 chunks ----------------
__global__ void scan_kernel()
{
    int bh = blockIdx.x;             // 0..63
    int t = threadIdx.x;
    float R[32];
    #pragma unroll
    for (int e = 0; e < 32; e++) R[e] = 0.f;
    for (int c = 0; c < NCHUNK; c++) {
        size_t bhc = (size_t)bh * NCHUNK + c;
        float decay = expf(g_Acs[bhc * CHUNK + CHUNK - 1]);
        size_t base = bhc * HEADDIM * DSTATE;
        #pragma unroll
        for (int e = 0; e < 32; e++) {
            size_t idx = base + t + (size_t)e * 256;
            g_pst[idx] = R[e];
            R[e] = fmaf(R[e], decay, g_cst[idx]);
        }
    }
}

// ---------------- Y = S@X + exp(Acs[l]) * C @ prev_state^T ----------------
__global__ void y_kernel()
{
    int ltile = blockIdx.x;
    int bhc = blockIdx.y;
    int c = bhc % NCHUNK;
    int bh = bhc / NCHUNK;
    int h = bh % NHEADS;
    int b = bh / NHEADS;
    int tid = threadIdx.x;
    int tx = tid & 15, ty = tid >> 4;
    int l0 = ltile * 64;
    __shared__ float s0a[16][64];
    __shared__ float s0b[16][64];
    float acc[4][4] = {};
    size_t rowbase = (size_t)(b * SEQLEN + c * CHUNK);
    size_t sc_base = (size_t)bhc * CHUNK * CHUNK;
    size_t abase = (size_t)bhc * CHUNK;
    size_t pbase = (size_t)bhc * HEADDIM * DSTATE;
    int ld_l = tid >> 2, ld_k4 = (tid & 3) * 4;
    int sx_s = tid >> 4, sx_p = (tid & 15) * 4;

    for (int s0 = 0; s0 < l0 + 64; s0 += 16) {
        #pragma unroll
        for (int j = 0; j < 4; j++)
            s0a[ld_k4 + j][ld_l] = g_scores[sc_base + (size_t)(l0 + ld_l) * CHUNK + s0 + ld_k4 + j];
        int srow = s0 + sx_s;
        float dtv = g_dt[(rowbase + srow) * NHEADS + h];
        #pragma unroll
        for (int j = 0; j < 4; j++)
            s0b[sx_s][sx_p + j] = g_xbc[(rowbase + srow) * CONVDIM + h * HEADDIM + sx_p + j] * dtv;
        __syncthreads();
        #pragma unroll
        for (int k = 0; k < 16; k++) {
            float a[4], bb[4];
            #pragma unroll
            for (int i = 0; i < 4; i++) a[i] = s0a[k][ty * 4 + i];
            #pragma unroll
            for (int i = 0; i < 4; i++) bb[i] = s0b[k][tx * 4 + i];
            #pragma unroll
            for (int i = 0; i < 4; i++)
                #pragma unroll
                for (int j = 0; j < 4; j++)
                    acc[i][j] = fmaf(a[i], bb[j], acc[i][j]);
        }
        __syncthreads();
    }

    float eA = expf(g_Acs[abase + l0 + ld_l]);
    for (int n0 = 0; n0 < DSTATE; n0 += 16) {
        #pragma unroll
        for (int j = 0; j < 4; j++)
            s0a[ld_k4 + j][ld_l] =
                g_xbc[(rowbase + l0 + ld_l) * CONVDIM + DINNER + DSTATE + n0 + ld_k4 + j] * eA;
        #pragma unroll
        for (int j = 0; j < 4; j++)
            s0b[ld_k4 + j][ld_l] = g_pst[pbase + (size_t)ld_l * DSTATE + n0 + ld_k4 + j];
        __syncthreads();
        #pragma unroll
        for (int k = 0; k < 16; k++) {
            float a[4], bb[4];
            #pragma unroll
            for (int i = 0; i < 4; i++) a[i] = s0a[k][ty * 4 + i];
            #pragma unroll
            for (int i = 0; i < 4; i++) bb[i] = s0b[k][tx * 4 + i];
            #pragma unroll
            for (int i = 0; i < 4; i++)
                #pragma unroll
                for (int j = 0; j < 4; j++)
                    acc[i][j] = fmaf(a[i], bb[j], acc[i][j]);
        }
        __syncthreads();
    }

    #pragma unroll
    for (int i = 0; i < 4; i++)
        #pragma unroll
        for (int j = 0; j < 4; j++)
            g_Y[(rowbase + l0 + ty * 4 + i) * DINNER + h * HEADDIM + tx * 4 + j] = acc[i][j];
}

// ---------------- layernorm (population var) * ln_w * silu(z) ----------------
__global__ void ln_gate_kernel(const float* __restrict__ ln_w)
{
    int row = blockIdx.x;
    int t = threadIdx.x;
    __shared__ float red[256];
    float vals[8];
    float sum = 0.f, sq = 0.f;
    #pragma unroll
    for (int i = 0; i < 8; i++) {
        float v = g_Y[(size_t)row * DINNER + t + i * 256];
        vals[i] = v;
        sum += v;
        sq = fmaf(v, v, sq);
    }
    red[t] = sum;
    __syncthreads();
    for (int off = 128; off; off >>= 1) {
        if (t < off) red[t] += red[t + off];
        __syncthreads();
    }
    float mean = red[0] / DINNER;
    __syncthreads();
    red[t] = sq;
    __syncthreads();
    for (int off = 128; off; off >>= 1) {
        if (t < off) red[t] += red[t + off];
        __syncthreads();
    }
    float var = red[0] / DINNER - mean * mean;
    float rstd = rsqrtf(var + LN_EPS);
    #pragma unroll
    for (int i = 0; i < 8; i++) {
        int j = t + i * 256;
        float z = g_zxbcdt[(size_t)row * DPROJ + j];
        float gate = z / (1.f + expf(-z));
        g_Yn[(size_t)row * DINNER + j] = (vals[i] - mean) * rstd * ln_w[j] * gate;
    }
}

// ---------------- launch ----------------
extern "C" void kernel_launch(void* const* d_in, const int* in_sizes, int n_in,
                              void* d_out, int out_size)
{
    const float* u          = (const float*)d_in[0];
    const float* in_proj_w  = (const float*)d_in[1];
    const float* conv_w     = (const float*)d_in[2];
    const float* conv_b     = (const float*)d_in[3];
    const float* dt_bias    = (const float*)d_in[4];
    const float* A_log      = (const float*)d_in[5];
    const float* ln_w       = (const float*)d_in[6];
    const float* out_proj_w = (const float*)d_in[7];
    float* out = (float*)d_out;

    float *zx_ptr, *yn_ptr;
    cudaGetSymbolAddress((void**)&zx_ptr, g_zxbcdt);
    cudaGetSymbolAddress((void**)&yn_ptr, g_Yn);

    // 1. in_proj: [4096,4384] = u[4096,1024] @ W^T   (tf32 tensor cores)
    gemm_tf32_kernel<<<dim3((DPROJ + TN - 1) / TN, ROWS / TM), 256>>>(
        u, in_proj_w, zx_ptr, ROWS, DPROJ, DMODEL);
    // 2. conv + silu
    conv_silu_kernel<<<(ROWS * CONVDIM + 255) / 256, 256>>>(conv_w, conv_b);
    // 3. dt / dA
    dt_kernel<<<(ROWS * NHEADS + 255) / 256, 256>>>(dt_bias, A_log);
    // 4. per-chunk cumsum
    cumsum_kernel<<<BHC, CHUNK>>>();
    // 5. scores
    scores_kernel<<<dim3(4, 4, BHC), 256>>>();
    // 6. chunk states
    cstate_kernel<<<BHC, 256>>>();
    // 7. inter-chunk scan
    scan_kernel<<<BATCH * NHEADS, 256>>>();
    // 8. Y = diag + off
    y_kernel<<<dim3(4, BHC), 256>>>();
    // 9. LN + gate
    ln_gate_kernel<<<ROWS, 256>>>(ln_w);
    // 10. out_proj: [4096,1024] = Yn[4096,2048] @ W^T  (tf32 tensor cores)
    gemm_tf32_kernel<<<dim3(DMODEL / TN, ROWS / TM), 256>>>(
        yn_ptr, out_proj_w, out, ROWS, DMODEL, DINNER);
}